// round 13
// baseline (speedup 1.0000x reference)
#include <cuda_runtime.h>
#include <math.h>

#define S_MAX   360
#define S_PAD   384                // zero-padded class-4 table
#define EPS_CLP 1e-6f
#define FULL    0xFFFFFFFFu
#define SPW     14                 // samples per warp (lanes 0..13 own one)
#define NWARP   8                  // warps per block
#define SPB     (SPW * NWARP)      // 112 samples per block
#define NSM     148                // grid rounded to 4 blocks/SM

// dot(u, qua_mul(y, q)) == v . q  with v = M(y)^T u (M orthogonal).
// argmin over concat([acos(d), acos(-d)]) == max over packed keys
//   key = (|d|_bits & ~0x1F) | (d>=0)<<4 | (15-s_low)
// priority: larger |d| -> half0 before half1 -> lower index. 5 truncated
// mantissa bits only affect tie-breaks among dots equal to within 2^-18
// relative. Zero-pad / skipped entries give key 0, never competitive.

__device__ __forceinline__ void compute_v(const float4 xv, const float4 yv,
                                          float& vx, float& vy, float& vz, float& vw)
{
    const float inv = rsqrtf(xv.x*xv.x + xv.y*xv.y + xv.z*xv.z + xv.w*xv.w);
    const float ux = xv.x*inv, uy = xv.y*inv, uz = xv.z*inv, uw = xv.w*inv;
    const float px = yv.x, py = yv.y, pz = yv.z, pw = yv.w;
    vx =  ux*pw - uy*pz + uz*py - uw*px;
    vy =  ux*pz + uy*pw - uz*px - uw*py;
    vz = -ux*py + uy*px + uz*pw - uw*pz;
    vw =  ux*px + uy*py + uz*pz + uw*pw;
}

__device__ __forceinline__ void write_result(float* __restrict__ out, int B, int b,
                                             const float4 xv, const float4 yv,
                                             const float4 q, float vbest, bool half0)
{
    const float loss = acosf(vbest);
    const float px = yv.x, py = yv.y, pz = yv.z, pw = yv.w;
    const float qx = q.x,  qy = q.y,  qz = q.z,  qw = q.w;
    const float rw = qw*pw - qx*px - qy*py - qz*pz;
    const float rx = qw*px + qx*pw + qy*pz - qz*py;
    const float ry = qw*py - qx*pz + qy*pw + qz*px;
    const float rz = qw*pz + qx*py - qy*px + qz*pw;
    const float sgn = half0 ? 1.0f : -1.0f;
    out[b] = loss;
    reinterpret_cast<float4*>(out + B)[b]   = make_float4(xv.x*sgn, xv.y*sgn, xv.z*sgn, xv.w*sgn);
    reinterpret_cast<float4*>(out + 5*B)[b] = make_float4(rx, ry, rz, rw);
}

__device__ __forceinline__ int pack_key(float d, int low)
{
    const int db = __float_as_int(d);
    return (db & 0x7FFFFFE0) | ((((~db) >> 31) & 1) << 4) | low;
}

__global__ __launch_bounds__(256, 4)
void quer_loss_kernel(const float*  __restrict__ x,
                      const float*  __restrict__ y,
                      const int*    __restrict__ n,
                      const float4* __restrict__ sym,   // [5*360] float4
                      float* __restrict__ out, int B)
{
    __shared__ float4 s4[S_PAD];     // class-4 table, zero-padded (6.1 KB)
    __shared__ float4 ss[4 * 12];    // classes 0..3, 12 entries each
    __shared__ int    qb [SPB];      // queued sample index
    __shared__ float4 qv4[SPB];      // queued v
    __shared__ int    cnt;

    const int tid  = threadIdx.x;
    const int lane = tid & 31;
    const int warp = tid >> 5;

    if (tid == 0) cnt = 0;
    for (int i = tid; i < S_PAD; i += 256)
        s4[i] = (i < S_MAX) ? __ldg(sym + 4 * S_MAX + i) : make_float4(0.f, 0.f, 0.f, 0.f);
    if (tid < 48)
        ss[tid] = __ldg(sym + (tid / 12) * S_MAX + (tid % 12));
    __syncthreads();

    const int base = blockIdx.x * SPB + warp * SPW;
    const int o = lane & 15;         // owned-sample slot (0..13 used)
    const int g = lane >> 4;         // group 0/1 handles entries 6g..6g+5
    const int b = base + o;
    const bool valid = (o < SPW) && (b < B);
    const int bl = valid ? b : (B - 1);

    const float4 xv = __ldg(reinterpret_cast<const float4*>(x) + bl);
    const float4 yv = __ldg(reinterpret_cast<const float4*>(y) + bl);
    const int cls   = __ldg(n + bl);

    float vx, vy, vz, vw;
    compute_v(xv, yv, vx, vy, vz, vw);

    // warp-aggregated enqueue of class-4 samples (one atomic per warp)
    {
        const bool big = valid && lane < 16 && (cls == 4);
        const unsigned mb = __ballot_sync(FULL, big);
        if (mb) {
            const int leader = __ffs(mb) - 1;
            int basep = 0;
            if (lane == leader) basep = atomicAdd(&cnt, __popc(mb));
            basep = __shfl_sync(FULL, basep, leader);
            if (big) {
                const int p = basep + __popc(mb & ((1u << lane) - 1));
                qb [p] = b;
                qv4[p] = make_float4(vx, vy, vz, vw);
            }
        }
    }

    // ---- small-class phase: 2 lanes per sample, 6 entries per lane ----
    {
        int kbest = 0;
        if (valid && cls != 4) {
            const int c = (cls == 0) ? 1 : (cls == 1) ? 2 : (cls == 2) ? 4 : 12;
            const int tb = cls * 12 + g * 6;
            #pragma unroll
            for (int k = 0; k < 6; ++k) {
                const int s = g * 6 + k;
                if (s < c) {
                    const float4 q = ss[tb + k];
                    const float d = vx*q.x + vy*q.y + vz*q.z + vw*q.w;
                    kbest = max(kbest, pack_key(d, 15 - s));
                }
            }
        }
        kbest = max(kbest, __shfl_xor_sync(FULL, kbest, 16));  // partner lane, same sample
        if (valid && lane < 16 && cls != 4) {
            const int  sbest = 15 - (kbest & 15);
            const bool half0 = (kbest >> 4) & 1;
            const float4 q = ss[cls * 12 + sbest];
            const float d = vx*q.x + vy*q.y + vz*q.z + vw*q.w;   // exact
            const float vbest = fminf(fabsf(d), 1.0f - EPS_CLP);
            write_result(out, B, b, xv, yv, q, vbest, half0);
        }
    }

    __syncthreads();                 // queue ready
    const int c4 = cnt;

    // ---- cooperative phase: warps pull balanced work from the queue ----
    for (int i = warp; i < c4; i += NWARP) {
        const float4 vv = qv4[i];    // uniform smem broadcasts

        // packed-key max over 12 elements; two alternating IMNMX chains
        int kA = 0, kB = 0;
        #pragma unroll
        for (int k = 0; k < 12; ++k) {
            const float4 q = s4[lane + k * 32];          // pads -> d = +0
            const float d = vv.x*q.x + vv.y*q.y + vv.z*q.z + vv.w*q.w;
            const int key = pack_key(d, 15 - k);
            if (k & 1) kB = max(kB, key); else kA = max(kA, key);
        }
        const int mykey = max(kA, kB);

        const int M = __reduce_max_sync(FULL, mykey);
        const unsigned who = __ballot_sync(FULL, mykey == M);

        if (lane == (int)(__ffs(who) - 1)) {             // lowest lane at max
            const int  kk    = 15 - (M & 15);
            const bool half0 = (M >> 4) & 1;
            const int  sbest = lane + kk * 32;
            const float4 q = s4[sbest];
            const float d = vv.x*q.x + vv.y*q.y + vv.z*q.z + vv.w*q.w;  // exact
            const float vbest = fminf(fabsf(d), 1.0f - EPS_CLP);
            const int bq = qb[i];
            const float4 xs = __ldg(reinterpret_cast<const float4*>(x) + bq);
            const float4 ys = __ldg(reinterpret_cast<const float4*>(y) + bq);
            write_result(out, B, bq, xs, ys, q, vbest, half0);
        }
    }
}

extern "C" void kernel_launch(void* const* d_in, const int* in_sizes, int n_in,
                              void* d_out, int out_size)
{
    // metadata order: x[B,4], y[B,4], pred_n[B,5] (unused), n[B],
    //                 sym_qua[5,360,4], sym_mask[5,360] (unused)
    const float*  x   = (const float*) d_in[0];
    const float*  y   = (const float*) d_in[1];
    const int*    n   = (const int*)   d_in[3];
    const float4* sym = (const float4*)d_in[4];
    float* out = (float*)d_out;

    const int B = in_sizes[3];                    // 65536
    int blocks = (B + SPB - 1) / SPB;             // 586
    blocks = ((blocks + NSM - 1) / NSM) * NSM;    // 592 = 4 blocks/SM exactly
    quer_loss_kernel<<<blocks, 256>>>(x, y, n, sym, out, B);
}

// round 14
// speedup vs baseline: 1.2418x; 1.2418x over previous
#include <cuda_runtime.h>
#include <math.h>

#define S_MAX   360
#define S_PAD   384                // zero-padded class-4 table
#define EPS_CLP 1e-6f
#define FULL    0xFFFFFFFFu
#define SPW     14                 // samples per warp (lanes 0..13 own one)
#define NWARP   8                  // warps per block
#define SPB     (SPW * NWARP)      // 112 samples per block
#define NSM     148                // grid rounded to 4 blocks/SM

// dot(u, qua_mul(y, q)) == v . q  with v = M(y)^T u (M orthogonal).
// argmin over concat([acos(d), acos(-d)]) == max over packed keys
//   key = (|d|_bits & ~0x1F) | (d>=0)<<4 | (15-s_low)
// priority: larger |d| -> half0 before half1 -> lower index -> lower lane
// (ballot/ffs). 5 truncated mantissa bits only affect tie-breaks among dots
// equal to within 2^-18 relative. Zero-pad / skipped entries give key 0.

__device__ __forceinline__ void compute_v(const float4 xv, const float4 yv,
                                          float& vx, float& vy, float& vz, float& vw)
{
    const float inv = rsqrtf(xv.x*xv.x + xv.y*xv.y + xv.z*xv.z + xv.w*xv.w);
    const float ux = xv.x*inv, uy = xv.y*inv, uz = xv.z*inv, uw = xv.w*inv;
    const float px = yv.x, py = yv.y, pz = yv.z, pw = yv.w;
    vx =  ux*pw - uy*pz + uz*py - uw*px;
    vy =  ux*pz + uy*pw - uz*px - uw*py;
    vz = -ux*py + uy*px + uz*pw - uw*pz;
    vw =  ux*px + uy*py + uz*pz + uw*pw;
}

__device__ __forceinline__ void write_result(float* __restrict__ out, int B, int b,
                                             const float4 xv, const float4 yv,
                                             const float4 q, float vbest, bool half0)
{
    const float loss = acosf(vbest);
    const float px = yv.x, py = yv.y, pz = yv.z, pw = yv.w;
    const float qx = q.x,  qy = q.y,  qz = q.z,  qw = q.w;
    const float rw = qw*pw - qx*px - qy*py - qz*pz;
    const float rx = qw*px + qx*pw + qy*pz - qz*py;
    const float ry = qw*py - qx*pz + qy*pw + qz*px;
    const float rz = qw*pz + qx*py - qy*px + qz*pw;
    const float sgn = half0 ? 1.0f : -1.0f;
    out[b] = loss;
    reinterpret_cast<float4*>(out + B)[b]   = make_float4(xv.x*sgn, xv.y*sgn, xv.z*sgn, xv.w*sgn);
    reinterpret_cast<float4*>(out + 5*B)[b] = make_float4(rx, ry, rz, rw);
}

__device__ __forceinline__ int pack_key(float d, int low)
{
    const int db = __float_as_int(d);
    return (db & 0x7FFFFFE0) | ((((~db) >> 31) & 1) << 4) | low;
}

__global__ __launch_bounds__(256, 4)
void quer_loss_kernel(const float*  __restrict__ x,
                      const float*  __restrict__ y,
                      const int*    __restrict__ n,
                      const float4* __restrict__ sym,   // [5*360] float4
                      float* __restrict__ out, int B)
{
    __shared__ float4 s4[S_PAD];     // class-4 table, zero-padded (6.1 KB)
    __shared__ float4 ss[4 * 12];    // classes 0..3, 12 entries each
    __shared__ int    qb [SPB];      // queued sample index
    __shared__ float4 qv4[SPB];      // queued v
    __shared__ int    win[SPB];      // winner: sbest | half0<<9
    __shared__ int    cnt;

    const int tid  = threadIdx.x;
    const int lane = tid & 31;
    const int warp = tid >> 5;

    if (tid == 0) cnt = 0;
    for (int i = tid; i < S_PAD; i += 256)
        s4[i] = (i < S_MAX) ? __ldg(sym + 4 * S_MAX + i) : make_float4(0.f, 0.f, 0.f, 0.f);
    if (tid < 48)
        ss[tid] = __ldg(sym + (tid / 12) * S_MAX + (tid % 12));
    __syncthreads();

    const int base = blockIdx.x * SPB + warp * SPW;
    const int o = lane & 15;         // owned-sample slot (0..13 used)
    const int g = lane >> 4;         // group 0/1 handles entries 6g..6g+5
    const int b = base + o;
    const bool valid = (o < SPW) && (b < B);
    const int bl = valid ? b : (B - 1);

    const float4 xv = __ldg(reinterpret_cast<const float4*>(x) + bl);
    const float4 yv = __ldg(reinterpret_cast<const float4*>(y) + bl);
    const int cls   = __ldg(n + bl);

    float vx, vy, vz, vw;
    compute_v(xv, yv, vx, vy, vz, vw);

    // warp-aggregated enqueue of class-4 samples (one atomic per warp)
    {
        const bool big = valid && lane < 16 && (cls == 4);
        const unsigned mb = __ballot_sync(FULL, big);
        if (mb) {
            const int leader = __ffs(mb) - 1;
            int basep = 0;
            if (lane == leader) basep = atomicAdd(&cnt, __popc(mb));
            basep = __shfl_sync(FULL, basep, leader);
            if (big) {
                const int p = basep + __popc(mb & ((1u << lane) - 1));
                qb [p] = b;
                qv4[p] = make_float4(vx, vy, vz, vw);
            }
        }
    }

    // ---- small-class phase: 2 lanes per sample, 6 entries per lane ----
    {
        int kbest = 0;
        if (valid && cls != 4) {
            const int c = (cls == 0) ? 1 : (cls == 1) ? 2 : (cls == 2) ? 4 : 12;
            const int tb = cls * 12 + g * 6;
            #pragma unroll
            for (int k = 0; k < 6; ++k) {
                const int s = g * 6 + k;
                if (s < c) {
                    const float4 q = ss[tb + k];
                    const float d = vx*q.x + vy*q.y + vz*q.z + vw*q.w;
                    kbest = max(kbest, pack_key(d, 15 - s));
                }
            }
        }
        kbest = max(kbest, __shfl_xor_sync(FULL, kbest, 16));  // partner lane
        if (valid && lane < 16 && cls != 4) {
            const int  sbest = 15 - (kbest & 15);
            const bool half0 = (kbest >> 4) & 1;
            const float4 q = ss[cls * 12 + sbest];
            const float d = vx*q.x + vy*q.y + vz*q.z + vw*q.w;   // exact
            const float vbest = fminf(fabsf(d), 1.0f - EPS_CLP);
            write_result(out, B, b, xv, yv, q, vbest, half0);
        }
    }

    __syncthreads();                 // queue ready
    const int c4 = cnt;

    // ---- cooperative phase: find winner only; epilogue batched below ----
    for (int i = warp; i < c4; i += NWARP) {
        const float4 vv = qv4[i];    // uniform smem broadcasts

        int kA = 0, kB = 0;          // two alternating IMNMX chains
        #pragma unroll
        for (int k = 0; k < 12; ++k) {
            const float4 q = s4[lane + k * 32];          // pads -> d = +0
            const float d = vv.x*q.x + vv.y*q.y + vv.z*q.z + vv.w*q.w;
            const int key = pack_key(d, 15 - k);
            if (k & 1) kB = max(kB, key); else kA = max(kA, key);
        }
        const int mykey = max(kA, kB);

        const int M = __reduce_max_sync(FULL, mykey);
        const unsigned who = __ballot_sync(FULL, mykey == M);
        if (lane == (int)(__ffs(who) - 1)) {             // lowest lane at max
            const int kk = 15 - (M & 15);
            win[i] = (lane + kk * 32) | (((M >> 4) & 1) << 9);
        }
    }

    __syncthreads();                 // winners ready

    // ---- batched epilogue: one big sample per thread, fully parallel ----
    for (int i = tid; i < c4; i += 256) {
        const int  w     = win[i];
        const int  sbest = w & 511;
        const bool half0 = (w >> 9) & 1;
        const int  bq    = qb[i];
        const float4 vv  = qv4[i];
        const float4 q   = s4[sbest];
        const float d = vv.x*q.x + vv.y*q.y + vv.z*q.z + vv.w*q.w;  // exact
        const float vbest = fminf(fabsf(d), 1.0f - EPS_CLP);
        const float4 xs = __ldg(reinterpret_cast<const float4*>(x) + bq);
        const float4 ys = __ldg(reinterpret_cast<const float4*>(y) + bq);
        write_result(out, B, bq, xs, ys, q, vbest, half0);
    }
}

extern "C" void kernel_launch(void* const* d_in, const int* in_sizes, int n_in,
                              void* d_out, int out_size)
{
    // metadata order: x[B,4], y[B,4], pred_n[B,5] (unused), n[B],
    //                 sym_qua[5,360,4], sym_mask[5,360] (unused)
    const float*  x   = (const float*) d_in[0];
    const float*  y   = (const float*) d_in[1];
    const int*    n   = (const int*)   d_in[3];
    const float4* sym = (const float4*)d_in[4];
    float* out = (float*)d_out;

    const int B = in_sizes[3];                    // 65536
    int blocks = (B + SPB - 1) / SPB;             // 586
    blocks = ((blocks + NSM - 1) / NSM) * NSM;    // 592 = 4 blocks/SM exactly
    quer_loss_kernel<<<blocks, 256>>>(x, y, n, sym, out, B);
}